// round 10
// baseline (speedup 1.0000x reference)
#include <cuda_runtime.h>

// Profile-HMM forward NLL + KLD -- wavefront, scaled linear domain.
// 512 one-warp blocks. Lane owns k = 2*lane+1, 2*lane+2. Probabilities linear;
// deferred power-of-2 rescale every 4 diagonals via redux.sync (lossless).
// All long-latency ops (3x SHFL, 2x LDS prefetch, redux) are issued at the
// BOTTOM of the loop body and consumed a full iteration later, so their
// latency is hidden behind ~60 independent instructions.

#define FULLMASK 0xffffffffu
#define LN2 0.69314718055994531f

__device__ float g_vb[512];
__device__ unsigned int g_cnt = 0;

__device__ __forceinline__ unsigned warp_max_u32(unsigned v) {
    unsigned r;
    asm volatile("redux.sync.max.u32 %0, %1, 0xffffffff;" : "=r"(r) : "r"(v));
    return r;
}

__global__ void __launch_bounds__(32) phmm_kernel(
    const int*   __restrict__ binput,    // (B, 256)
    const float* __restrict__ trans,     // (B, 65, 7) log-probs (nats)
    const float* __restrict__ emis,      // (B, 64, 4) log-probs (nats)
    const float* __restrict__ mus,       // (B, 16)
    const float* __restrict__ logvars,   // (B, 16)
    float*       __restrict__ out)
{
    constexpr int L = 256;
    constexpr int K = 64;
    const int b    = blockIdx.x;
    const int lane = threadIdx.x;

    // s_co_p: 64 front-pad + 256 symbols + back-pad, value = symbol*32
    __shared__ int    s_co_p[416];
    __shared__ float2 ep[128];           // [4 symbols][32 lanes] {e1, e2}

    const int* bi = binput + b * L;
#pragma unroll
    for (int i = 0; i < 13; ++i) {
        const int idx = lane + 32 * i;   // covers [0, 416)
        int v = 0;
        if (idx >= 64 && idx < 320) v = bi[idx - 64] << 5;
        s_co_p[idx] = v;
    }

    const float* a  = trans + b * 65 * 7;
    const float* em = emis  + b * 64 * 4;

    const int k1 = 2 * lane + 1;                // slot1 owns k1, slot2 owns k1+1
    const float* r0 = a + (k1 - 1) * 7;         // transition row k1-1
    const float* r1 = r0 + 7;                   // row k1 (= row k2-1)
    const float* r2 = r1 + 7;                   // row k2

    // indices: M2M=0, M2I=1, M2D=2, I2M=3, I2I=4, D2M=5, D2D=6
    // LOG_Q (q=0.25) folded into aMI/aII.
    const float aMM1 = expf(r0[0]), aMD1 = expf(r0[2]);
    const float aIM1 = expf(r0[3]), aDM1 = expf(r0[5]), aDD1 = expf(r0[6]);
    const float aMI1 = 0.25f * expf(r1[1]), aII1 = 0.25f * expf(r1[4]);
    const float aMM2 = expf(r1[0]), aMD2 = expf(r1[2]);
    const float aIM2 = expf(r1[3]), aDM2 = expf(r1[5]), aDD2 = expf(r1[6]);
    const float aMI2 = 0.25f * expf(r2[1]), aII2 = 0.25f * expf(r2[4]);
    const float aMI0 = 0.25f * expf(a[1]),  aII0 = 0.25f * expf(a[4]);   // row 0

#pragma unroll
    for (int c = 0; c < 4; ++c)
        ep[c * 32 + lane] = make_float2(expf(em[(k1 - 1) * 4 + c]),
                                        expf(em[k1 * 4 + c]));
    __syncwarp();

    // loop-carried state (all scaled by 2^Sacc relative to absolute probs)
    float cM1 = 0.f, cI1 = 0.f, cD1 = 0.f, pM1 = 0.f, pI1 = 0.f, pD1 = 0.f;
    float cM2 = 0.f, cI2 = 0.f, cD2 = 0.f, pM2 = 0.f, pI2 = 0.f, pD2 = 0.f;
    const float M00 = 1.152921504606847e18f;    // M(0,0) = 1 * 2^60
    float inj   = exp2f(-84.26950408889634f);   // e^-100 * 2^60  (NEG boundary)
    float k0I   = inj;                          // I(0,0) = NEG
    float mprev = M00;
    int   Sacc  = 60;
    // deferred rescale: scale computed from window t, applied at window t+1
    float sc_ap = 1.0f;
    int   se_ap = 0;

    // primed neighbor values for t=1 (diag 0): lane-1 state is all zero;
    // lane 0 sees the k=0 column at l=0: {M00, I(0,0)=inj, inj}
    float nM = (lane == 0) ? M00 : 0.f;
    float nI = (lane == 0) ? inj : 0.f;
    float nD = (lane == 0) ? inj : 0.f;
    float qM = 0.f, qI = 0.f, qD = 0.f;  // diag -1 neighbors: dead

    // emission pipeline priming (t=1): P = pack for e1(1); off_p feeds P(2)
    int    off_p = s_co_p[65 - k1];
    float2 P     = ep[s_co_p[64 - k1] + lane];
    float  e2c   = 0.0f;                // e2(1) is don't-care (cell dead)

#pragma unroll 4
    for (int t = 1; t <= L + K; ++t) {
        const float e1 = P.x;
        const float e2 = e2c;
        const int l1 = t - k1;

        // ---- slot1: cell (l1, k1) ----
        float M1g = e1 * fmaf(aDM1, qD, fmaf(aIM1, qI, aMM1 * qM));
        float I1g = fmaf(aII1, cI1, aMI1 * cM1);
        float D1n = fmaf(aDD1, nD, aMD1 * nM);
        float M1n = (l1 == 0) ? inj : M1g;
        float I1n = (l1 == 0) ? inj : I1g;

        // ---- slot2: cell (l1-1, k1+1); q-cell = p*1, n-cell = c*1 ----
        float M2g = e2 * fmaf(aDM2, pD1, fmaf(aIM2, pI1, aMM2 * pM1));
        float I2g = fmaf(aII2, cI2, aMI2 * cM2);
        float D2n = fmaf(aDD2, cD1, aMD2 * cM1);
        float M2n = (l1 == 1) ? inj : M2g;
        float I2n = (l1 == 1) ? inj : I2g;

        // unconditional rotation + neighbor carry (n of iter t becomes q of t+1)
        pM2 = cM2; pI2 = cI2; pD2 = cD2; cM2 = M2n; cI2 = I2n; cD2 = D2n;
        pM1 = cM1; pI1 = cI1; pD1 = cD1; cM1 = M1n; cI1 = I1n; cD1 = D1n;
        qM = nM; qI = nI; qD = nD;

        // ---- k=0 column advance to diag t:  I(t,0), M(t,0)=NEG ----
        k0I = fmaf(aII0, k0I, aMI0 * mprev);
        mprev = inj;

        // ---- shuffle neighbor (k-1) values for iter t+1 (latency hidden) ----
        nM = __shfl_up_sync(FULLMASK, cM2, 1);
        nI = __shfl_up_sync(FULLMASK, cI2, 1);
        nD = __shfl_up_sync(FULLMASK, cD2, 1);
        if (lane == 0) { nM = mprev; nI = k0I; nD = inj; }

        // ---- emission prefetch advance (latency hidden) ----
        e2c = P.y;
        P = ep[off_p + lane];            // pack for iter t+1
        off_p = s_co_p[t - k1 + 65];     // s_co offset for iter t+2

        // ---- deferred power-of-2 rescale every 4 diagonals ----
        if ((t & 3) == 0) {
            // apply the scale computed at the PREVIOUS window
            cM1 *= sc_ap; cI1 *= sc_ap; cD1 *= sc_ap;
            pM1 *= sc_ap; pI1 *= sc_ap; pD1 *= sc_ap;
            cM2 *= sc_ap; cI2 *= sc_ap; cD2 *= sc_ap;
            pM2 *= sc_ap; pI2 *= sc_ap; pD2 *= sc_ap;
            nM  *= sc_ap; nI  *= sc_ap; nD  *= sc_ap;
            qM  *= sc_ap; qI  *= sc_ap; qD  *= sc_ap;
            k0I *= sc_ap; mprev *= sc_ap; inj *= sc_ap;
            Sacc += se_ap;
            // start the next window's reduction (consumed 4 iters from now)
            float m = fmaxf(fmaxf(cM1, cM2), fmaxf(cI1, cI2));
            m = fmaxf(m, fmaxf(cD1, cD2));
            m = fmaxf(m, k0I);
            const unsigned mu32 = warp_max_u32(__float_as_uint(m));
            const int E = (int)(mu32 >> 23) & 0xFF;            // biased exponent
            int se = 187 - E;                                  // 60 - (E - 127)
            se = min(max(se, 0), 120);
            se_ap = se;
            sc_ap = __int_as_float((se + 127) << 23);          // 2^se (exact)
        }
    }

    // lane 31 slot2 holds (M, I, D) at (L, K); broadcast to all lanes
    const float MF = __shfl_sync(FULLMASK, cM2, 31);
    const float IF = __shfl_sync(FULLMASK, cI2, 31);
    const float DF = __shfl_sync(FULLMASK, cD2, 31);
    const float fM = expf(a[K * 7 + 0]);
    const float fI = expf(a[K * 7 + 3]);
    const float fD = expf(a[K * 7 + 5]);
    const float sum = fmaf(fD, DF, fmaf(fI, IF, fM * MF));
    const float nll = -(log2f(sum) - (float)Sacc) * LN2;

    // KLD term: -0.5 * sum_e (1 + lv - mu^2 - exp(lv))
    float term = 0.0f;
    if (lane < 16) {
        const float mu = mus[b * 16 + lane];
        const float lv = logvars[b * 16 + lane];
        term = 1.0f + lv - mu * mu - expf(lv);
    }
#pragma unroll
    for (int o = 16; o > 0; o >>= 1) term += __shfl_xor_sync(FULLMASK, term, o);

    if (lane == 0) g_vb[b] = nll - 0.5f * term;

    // ---- last-block-done final reduction (deterministic fixed-order sum) ----
    __threadfence();
    unsigned int old = 0;
    if (lane == 0) old = atomicAdd(&g_cnt, 1u);
    old = __shfl_sync(FULLMASK, old, 0);
    if (old == gridDim.x - 1) {
        __threadfence();
        float s = 0.0f;
#pragma unroll
        for (int i = 0; i < 16; ++i) s += g_vb[lane + 32 * i];
#pragma unroll
        for (int o = 16; o > 0; o >>= 1) s += __shfl_xor_sync(FULLMASK, s, o);
        if (lane == 0) { out[0] = s * (1.0f / 512.0f); g_cnt = 0; }
    }
}

extern "C" void kernel_launch(void* const* d_in, const int* in_sizes, int n_in,
                              void* d_out, int out_size) {
    const int*   batch_input = (const int*)  d_in[0];
    const float* trans       = (const float*)d_in[1];
    const float* emisp       = (const float*)d_in[2];
    const float* mus         = (const float*)d_in[3];
    const float* logvars     = (const float*)d_in[4];
    (void)in_sizes; (void)n_in; (void)out_size;

    phmm_kernel<<<512, 32>>>(batch_input, trans, emisp, mus, logvars, (float*)d_out);
}